// round 14
// baseline (speedup 1.0000x reference)
#include <cuda_runtime.h>
#include <cuda_fp16.h>
#include <math.h>
#include <stdint.h>

#define HW    8836       // 94*94
#define PER_B 70688      // 8 * HW
#define HALFB 35344      // PER_B/2
#define NPTS  565504     // 8 batches * PER_B
#define EPSS  1e-8f

// u layout: [b][dcap][Dz][c][hw]  => plane index ((b*8+dcap)*8+Dz)*32+c, innermost hw
__device__ __half g_u[8 * 8 * 8 * 32 * 8836];  // 290 MB scratch (fp16)
__device__ __half g_M[36 * NPTS];              // per-point 8x8 Gram (upper tri), SoA, fp16
__device__ float g_bq[8 * NPTS];               // routing logits b, SoA
__device__ float g_S1[64];
__device__ float g_S2[64];
__device__ __half g_wh[256 * 144];             // weights fp16, [co][perm(k)]
// im2col, fp16 k-pair packed: word [slice][kp][hw] = (k=2kp, k=2kp+1) at point hw
__device__ uint32_t g_im[64 * 72 * 8836 + 128];  // 163 MB

__device__ __forceinline__ uint32_t smem_u32(const void* p) {
    uint32_t a;
    asm("{ .reg .u64 t; cvta.to.shared.u64 t, %1; cvt.u32.u64 %0, t; }" : "=r"(a) : "l"(p));
    return a;
}
__device__ __forceinline__ uint32_t packh2(float lo, float hi) {
    uint32_t r;
    asm("cvt.rn.f16x2.f32 %0, %1, %2;" : "=r"(r) : "f"(hi), "f"(lo));
    return r;
}
__device__ __forceinline__ void cpa16(uint32_t dst, const void* src) {
    asm volatile("cp.async.cg.shared.global [%0], [%1], 16;"
                 :: "r"(dst), "l"(src) : "memory");
}
#define CP_COMMIT() asm volatile("cp.async.commit_group;" ::: "memory")

__device__ __forceinline__ void mma16816(float c[4],
                                         uint32_t a0, uint32_t a1, uint32_t a2, uint32_t a3,
                                         uint32_t b0, uint32_t b1) {
    asm volatile(
        "mma.sync.aligned.m16n8k16.row.col.f32.f16.f16.f32 "
        "{%0,%1,%2,%3}, {%4,%5,%6,%7}, {%8,%9}, {%0,%1,%2,%3};"
        : "+f"(c[0]), "+f"(c[1]), "+f"(c[2]), "+f"(c[3])
        : "r"(a0), "r"(a1), "r"(a2), "r"(a3), "r"(b0), "r"(b1));
}

// ---------------- weight fp16 convert + k-permute (once, tiny) ----------------
__global__ void wconv_kernel(const float* __restrict__ w) {
    int i = blockIdx.x * 256 + threadIdx.x;   // 36864 = 256co * 144k
    if (i < 36864) {
        int co = i / 144, k = i - co * 144;
        int j = k & 15;
        int pos = 4 * ((j & 7) >> 1) + (j & 1) + 2 * (j >> 3);
        g_wh[co * 144 + (k & ~15) + pos] = __float2half_rn(w[i]);
    }
}

// ---------------- im2col pre-pass: 8 outputs/thread, incremental pointers ----------------
__global__ __launch_bounds__(256) void im2col_kernel(const float* __restrict__ x) {
    int kp = blockIdx.y;       // 0..71
    int slice = blockIdx.z;    // 0..63
    int b = slice >> 3, Dz = slice & 7;
    const float* xp = x + ((size_t)(b * 16) * 8 + Dz) * 9216;
    int k0 = 2 * kp;
    int ci0 = k0 / 9, r0 = k0 - ci0 * 9, kh0 = r0 / 3, kw0 = r0 - kh0 * 3;
    int k1 = k0 + 1;
    int ci1 = k1 / 9, r1 = k1 - ci1 * 9, kh1 = r1 / 3, kw1 = r1 - kh1 * 3;

    int lane = threadIdx.x & 31;
    int warp = threadIdx.x >> 5;
    int p = blockIdx.x * 2048 + warp * 256 + lane;  // lane-consecutive -> coalesced
    int y = p / 94, xx = p - y * 94;
    const float* s0 = xp + (size_t)ci0 * 73728 + (y + kh0) * 96 + xx + kw0;
    const float* s1 = xp + (size_t)ci1 * 73728 + (y + kh1) * 96 + xx + kw1;
    uint32_t* dst = g_im + ((size_t)slice * 72 + kp) * 8836 + p;

    #pragma unroll
    for (int i = 0; i < 8; i++) {
        if (p < HW) dst[0] = packh2(s0[0], s1[0]);
        p += 32; dst += 32;
        xx += 32;
        int step = (xx >= 94) ? 34 : 32;     // +2 row-pad skip on wrap
        xx -= (xx >= 94) ? 94 : 0;
        s0 += step; s1 += step;
    }
}

// ---------------- conv via mma.sync fp16, im2col-fed B, N=64 tile / 3 CTA/SM ----------------
// A: fp16 [128 m][144 k permuted], cp.async once (region reused as fp16 C stage).
// B: u32 fp16x2 [24 kp][72 n-stride] per chunk buffer, cpa16 double-buffered.
#define KC     48
#define NCHUNK 3
#define BSTR   72
#define NTILE  64
#define ABYTES (128 * 144 * 2)          // 36864
#define BBYTES (24 * BSTR * 4)          // 6912
#define SMEM_TOT (ABYTES + 2 * BBYTES)  // 50688
#define STG_H  72                       // C stage row stride in halves (144 B)

__global__ __launch_bounds__(256, 3) void conv_mma_kernel() {
    extern __shared__ char smc[];
    uint32_t smem_base = smem_u32(smc);

    int tid = threadIdx.x, wid = tid >> 5, lid = tid & 31;
    int gid = lid >> 2, tig = lid & 3;

    int tileBase = blockIdx.x * NTILE;
    int mGroup   = blockIdx.y;           // 0..1
    int bd       = blockIdx.z;           // 0..63 slice
    int b = bd >> 3, Dz = bd & 7;

    // A fill (once): 128 rows x 18 16B-vectors = 2304 ops, 9/thread
    {
        const __half* wsrc = g_wh + (size_t)mGroup * 128 * 144;
        #pragma unroll
        for (int i = 0; i < 9; i++) {
            int e = tid + i * 256;
            int m = e / 18, v = e - m * 18;
            cpa16(smem_base + (uint32_t)(m * 288 + v * 16),
                  wsrc + (size_t)m * 144 + v * 8);
        }
    }

    const uint32_t* imBase = g_im + (size_t)bd * 72 * 8836 + tileBase;

    // B fill: 24 kp x 16 4-word groups = 384 cpa16, 1.5/thread
    auto prefetchB = [&](int c, int buf) {
        uint32_t bBase = smem_base + ABYTES + (uint32_t)buf * BBYTES;
        const uint32_t* src = imBase + (size_t)(c * 24) * 8836;
        #pragma unroll
        for (int i = 0; i < 2; i++) {
            int e = tid + i * 256;          // 0..511, use 0..383
            if (e < 384) {
                int kp = e >> 4, t = e & 15;
                cpa16(bBase + (uint32_t)(kp * BSTR + 4 * t) * 4,
                      src + (size_t)kp * 8836 + 4 * t);
            }
        }
        CP_COMMIT();
    };

    int m0 = (wid & 1) * 64;
    int n0 = (wid >> 1) * 16;

    float acc[4][2][4];
    #pragma unroll
    for (int i = 0; i < 4; i++)
        #pragma unroll
        for (int j = 0; j < 2; j++)
            #pragma unroll
            for (int q = 0; q < 4; q++) acc[i][j][q] = 0.f;

    prefetchB(0, 0);   // group 0 = A + B0

    const __half* Ah = (const __half*)smc;

    #pragma unroll
    for (int c = 0; c < NCHUNK; c++) {
        if (c + 1 < NCHUNK) {
            prefetchB(c + 1, (c + 1) & 1);
            asm volatile("cp.async.wait_group 1;" ::: "memory");
        } else {
            asm volatile("cp.async.wait_group 0;" ::: "memory");
        }
        __syncthreads();

        const uint32_t* Bcur = (const uint32_t*)(smc + ABYTES + (c & 1) * BBYTES);

        #pragma unroll
        for (int ks = 0; ks < KC / 16; ks++) {
            int kbA = c * KC + ks * 16;   // A global k base (permuted layout)
            uint32_t a[4][4], bb[2][2];
            #pragma unroll
            for (int mf = 0; mf < 4; mf++) {
                int m = m0 + mf * 16 + gid;
                uint2 v0 = *(const uint2*)(Ah + m * 144 + kbA + 4 * tig);
                uint2 v1 = *(const uint2*)(Ah + (m + 8) * 144 + kbA + 4 * tig);
                a[mf][0] = v0.x;   // A[m][k,k+1]
                a[mf][1] = v1.x;   // A[m+8][k,k+1]
                a[mf][2] = v0.y;   // A[m][k+8,k+9]
                a[mf][3] = v1.y;   // A[m+8][k+8,k+9]
            }
            int kp0 = ks * 8 + tig;
            #pragma unroll
            for (int nf = 0; nf < 2; nf++) {
                int n = n0 + nf * 8 + gid;
                bb[nf][0] = Bcur[kp0 * BSTR + n];            // (k, k+1) fp16x2
                bb[nf][1] = Bcur[(kp0 + 4) * BSTR + n];      // (k+8, k+9)
            }
            #pragma unroll
            for (int mf = 0; mf < 4; mf++)
                #pragma unroll
                for (int nf = 0; nf < 2; nf++)
                    mma16816(acc[mf][nf], a[mf][0], a[mf][1], a[mf][2], a[mf][3],
                             bb[nf][0], bb[nf][1]);
        }
        __syncthreads();
    }

    // ---- epilogue: stage C fp16 into dead A region [128 co_loc][STG_H], then coalesced out ----
    __half* stage = (__half*)smc;
    #pragma unroll
    for (int mf = 0; mf < 4; mf++) {
        #pragma unroll
        for (int h2 = 0; h2 < 2; h2++) {
            int col = m0 + mf * 16 + gid + h2 * 8;   // co_local 0..127
            int n = n0 + 2 * tig;
            #pragma unroll
            for (int nf = 0; nf < 2; nf++) {
                *(__half2*)(stage + col * STG_H + n + nf * 8) =
                    __floats2half2_rn(acc[mf][nf][h2 * 2], acc[mf][nf][h2 * 2 + 1]);
            }
        }
    }
    __syncthreads();

    int nvalid = HW - tileBase;
    int segLim = (nvalid >= NTILE) ? 16 : (nvalid >> 2);   // uint2 = 4 halves
    #pragma unroll
    for (int i = 0; i < 8; i++) {
        int e = tid + i * 256;           // 0..2047
        int col = e >> 4, seg = e & 15;
        if (seg < segLim) {
            int co = mGroup * 128 + col;
            int dcap = co & 7, ccap = co >> 3;
            __half* dst = g_u + ((size_t)((b * 8 + dcap) * 8 + Dz) * 32 + ccap) * 8836
                          + tileBase + seg * 4;
            *(uint2*)dst = *(const uint2*)(stage + col * STG_H + seg * 4);
        }
    }
}

// ============================ routing (2 points/thread) ============================
__global__ void init_kernel() {
    int t = threadIdx.x;
    if (t < 64) { g_S1[t] = 0.f; g_S2[t] = 0.f; }
}

__device__ __forceinline__ void blockReduceAtomic(float e[8], int b, float* Sg) {
    __shared__ float red[8][8];
    #pragma unroll
    for (int off = 16; off > 0; off >>= 1)
        #pragma unroll
        for (int d = 0; d < 8; d++) e[d] += __shfl_down_sync(0xffffffffu, e[d], off);
    int lane = threadIdx.x & 31, wp = threadIdx.x >> 5;
    if (lane == 0) {
        #pragma unroll
        for (int d = 0; d < 8; d++) red[wp][d] = e[d];
    }
    __syncthreads();
    if (threadIdx.x < 8) {
        float s = 0.f;
        #pragma unroll
        for (int w_ = 0; w_ < 8; w_++) s += red[w_][threadIdx.x];
        atomicAdd(&Sg[b * 8 + threadIdx.x], s);
    }
}

__global__ __launch_bounds__(256) void gram_iter0_kernel() {
    int b = blockIdx.y;
    int idx = blockIdx.x * 256 + threadIdx.x;
    bool act = idx < HALFB;
    float e[8];
    if (act) {
        int pl = idx * 2;
        int dcap = pl / 8836;
        int hw = pl - dcap * 8836;
        const __half2* up = (const __half2*)(g_u + ((size_t)(b * 8 + dcap) * 256) * 8836 + hw);

        __half2 M2[36];
        #pragma unroll
        for (int i = 0; i < 36; i++) M2[i] = __float2half2_rn(0.f);

        #pragma unroll 4
        for (int c = 0; c < 32; c++) {
            __half2 a2[8];
            #pragma unroll
            for (int d = 0; d < 8; d++) a2[d] = up[(size_t)(d * 32 + c) * 4418];
            int mi = 0;
            #pragma unroll
            for (int d1 = 0; d1 < 8; d1++)
                #pragma unroll
                for (int d2 = d1; d2 < 8; d2++) {
                    M2[mi] = __hfma2(a2[d1], a2[d2], M2[mi]);
                    mi++;
                }
        }

        float rsA[8], rsB[8];
        #pragma unroll
        for (int d = 0; d < 8; d++) { rsA[d] = 0.f; rsB[d] = 0.f; }
        {
            int mi = 0;
            #pragma unroll
            for (int d1 = 0; d1 < 8; d1++)
                #pragma unroll
                for (int d2 = d1; d2 < 8; d2++) {
                    float2 m = __half22float2(M2[mi++]);
                    rsA[d2] += m.x; rsB[d2] += m.y;
                    if (d1 != d2) { rsA[d1] += m.x; rsB[d1] += m.y; }
                }
        }
        float totA = 0.f, totB = 0.f;
        #pragma unroll
        for (int d = 0; d < 8; d++) { totA += rsA[d]; totB += rsB[d]; }
        const float invN = 1.0f / 70688.0f;
        float n2A = totA * invN * invN, n2B = totB * invN * invN;
        float h0A = (n2A / (1.f + n2A)) / sqrtf(n2A + EPSS);
        float h0B = (n2B / (1.f + n2B)) / sqrtf(n2B + EPSS);

        int pg = b * PER_B + pl;
        #pragma unroll
        for (int i = 0; i < 36; i++)
            *(__half2*)(g_M + (size_t)i * NPTS + pg) = M2[i];
        #pragma unroll
        for (int d = 0; d < 8; d++) {
            float bvA = h0A * invN * rsA[d];
            float bvB = h0B * invN * rsB[d];
            *(float2*)(g_bq + (size_t)d * NPTS + pg) = make_float2(bvA, bvB);
            e[d] = expf(bvA) + expf(bvB);
        }
    } else {
        #pragma unroll
        for (int d = 0; d < 8; d++) e[d] = 0.f;
    }
    blockReduceAtomic(e, b, g_S1);
}

__global__ __launch_bounds__(256) void iter1_kernel() {
    int b = blockIdx.y;
    int idx = blockIdx.x * 256 + threadIdx.x;
    bool act = idx < HALFB;
    float e[8];
    if (act) {
        int pg = b * PER_B + idx * 2;
        float2 bl[8];
        float ccA[8], ccB[8];
        #pragma unroll
        for (int d = 0; d < 8; d++) {
            bl[d] = *(const float2*)(g_bq + (size_t)d * NPTS + pg);
            float S = g_S1[b * 8 + d];
            ccA[d] = expf(bl[d].x) / S;
            ccB[d] = expf(bl[d].y) / S;
        }
        float tA[8], tB[8];
        #pragma unroll
        for (int d = 0; d < 8; d++) { tA[d] = 0.f; tB[d] = 0.f; }
        {
            int mi = 0;
            #pragma unroll
            for (int d1 = 0; d1 < 8; d1++)
                #pragma unroll
                for (int d2 = d1; d2 < 8; d2++) {
                    float2 m = __half22float2(*(const __half2*)(g_M + (size_t)mi * NPTS + pg));
                    tA[d2] += m.x * ccA[d1]; tB[d2] += m.y * ccB[d1];
                    if (d1 != d2) { tA[d1] += m.x * ccA[d2]; tB[d1] += m.y * ccB[d2]; }
                    mi++;
                }
        }
        float n2A = 0.f, n2B = 0.f;
        #pragma unroll
        for (int d = 0; d < 8; d++) { n2A += ccA[d] * tA[d]; n2B += ccB[d] * tB[d]; }
        float h1A = (n2A / (1.f + n2A)) / sqrtf(n2A + EPSS);
        float h1B = (n2B / (1.f + n2B)) / sqrtf(n2B + EPSS);
        #pragma unroll
        for (int d = 0; d < 8; d++) {
            float bnA = bl[d].x + h1A * tA[d];
            float bnB = bl[d].y + h1B * tB[d];
            *(float2*)(g_bq + (size_t)d * NPTS + pg) = make_float2(bnA, bnB);
            e[d] = expf(bnA) + expf(bnB);
        }
    } else {
        #pragma unroll
        for (int d = 0; d < 8; d++) e[d] = 0.f;
    }
    blockReduceAtomic(e, b, g_S2);
}

__global__ __launch_bounds__(256) void final_kernel(float* __restrict__ out) {
    int b = blockIdx.y;
    int idx = blockIdx.x * 256 + threadIdx.x;
    if (idx >= HALFB) return;
    int pl = idx * 2;
    int pg = b * PER_B + pl;
    float ccA[8], ccB[8];
    #pragma unroll
    for (int d = 0; d < 8; d++) {
        float2 bv = *(const float2*)(g_bq + (size_t)d * NPTS + pg);
        float S = g_S2[b * 8 + d];
        ccA[d] = expf(bv.x) / S;
        ccB[d] = expf(bv.y) / S;
    }

    int dcap = pl / 8836, hw = pl - dcap * 8836;
    const __half2* up = (const __half2*)(g_u + ((size_t)(b * 8 + dcap) * 256) * 8836 + hw);
    #pragma unroll 4
    for (int c = 0; c < 32; c++) {
        float sA = 0.f, sB = 0.f;
        #pragma unroll
        for (int d = 0; d < 8; d++) {
            float2 uf = __half22float2(up[(size_t)(d * 32 + c) * 4418]);
            sA += ccA[d] * uf.x;
            sB += ccB[d] * uf.y;
        }
        *(float2*)(out + ((size_t)(b * 32 + c) * 8 + dcap) * 8836 + hw) = make_float2(sA, sB);
    }
}

extern "C" void kernel_launch(void* const* d_in, const int* in_sizes, int n_in,
                              void* d_out, int out_size) {
    const float* x = (const float*)d_in[0];
    const float* w = (const float*)d_in[1];
    float* out = (float*)d_out;

    cudaFuncSetAttribute(conv_mma_kernel, cudaFuncAttributeMaxDynamicSharedMemorySize, SMEM_TOT);

    init_kernel<<<1, 64>>>();
    wconv_kernel<<<144, 256>>>(w);

    dim3 igrid(5, 72, 64);   // 2048-p tiles x kp x slices, 8 outputs/thread
    im2col_kernel<<<igrid, 256>>>(x);

    dim3 cgrid(139, 2, 64);  // 64-wide n-tiles x co-halves x (b,Dz)
    conv_mma_kernel<<<cgrid, 256, SMEM_TOT>>>();

    dim3 rgrid(139, 8);      // ceil(35344/256) x 8 batches, 2 pts/thread
    gram_iter0_kernel<<<rgrid, 256>>>();
    iter1_kernel<<<rgrid, 256>>>();
    final_kernel<<<rgrid, 256>>>(out);
}

// round 15
// speedup vs baseline: 1.1108x; 1.1108x over previous
#include <cuda_runtime.h>
#include <cuda_fp16.h>
#include <math.h>
#include <stdint.h>

#define HW    8836       // 94*94
#define PER_B 70688      // 8 * HW
#define HALFB 35344      // PER_B/2
#define NPTS  565504     // 8 batches * PER_B
#define EPSS  1e-8f

// u layout: [b][dcap][Dz][c][hw]  => plane index ((b*8+dcap)*8+Dz)*32+c, innermost hw
__device__ __half g_u[8 * 8 * 8 * 32 * 8836];  // 290 MB scratch (fp16)
__device__ __half g_M[36 * NPTS];              // per-point 8x8 Gram (upper tri), SoA, fp16
__device__ float g_bq[8 * NPTS];               // routing logits b, SoA
__device__ float g_S1[64];
__device__ float g_S2[64];
__device__ __half g_wh[256 * 144];             // weights fp16, [co][perm(k)]
// im2col, fp16 k-pair packed: word [slice][kp][hw] = (k=2kp, k=2kp+1) at point hw
__device__ uint32_t g_im[64 * 72 * 8836 + 128];  // 163 MB

__device__ __forceinline__ uint32_t smem_u32(const void* p) {
    uint32_t a;
    asm("{ .reg .u64 t; cvta.to.shared.u64 t, %1; cvt.u32.u64 %0, t; }" : "=r"(a) : "l"(p));
    return a;
}
__device__ __forceinline__ uint32_t packh2(float lo, float hi) {
    uint32_t r;
    asm("cvt.rn.f16x2.f32 %0, %1, %2;" : "=r"(r) : "f"(hi), "f"(lo));
    return r;
}
__device__ __forceinline__ void cpa16(uint32_t dst, const void* src) {
    asm volatile("cp.async.cg.shared.global [%0], [%1], 16;"
                 :: "r"(dst), "l"(src) : "memory");
}
#define CP_COMMIT() asm volatile("cp.async.commit_group;" ::: "memory")

__device__ __forceinline__ void mma16816(float c[4],
                                         uint32_t a0, uint32_t a1, uint32_t a2, uint32_t a3,
                                         uint32_t b0, uint32_t b1) {
    asm volatile(
        "mma.sync.aligned.m16n8k16.row.col.f32.f16.f16.f32 "
        "{%0,%1,%2,%3}, {%4,%5,%6,%7}, {%8,%9}, {%0,%1,%2,%3};"
        : "+f"(c[0]), "+f"(c[1]), "+f"(c[2]), "+f"(c[3])
        : "r"(a0), "r"(a1), "r"(a2), "r"(a3), "r"(b0), "r"(b1));
}

// ---------------- weight fp16 convert + k-permute (once, tiny) ----------------
__global__ void wconv_kernel(const float* __restrict__ w) {
    int i = blockIdx.x * 256 + threadIdx.x;   // 36864 = 256co * 144k
    if (i < 36864) {
        int co = i / 144, k = i - co * 144;
        int j = k & 15;
        int pos = 4 * ((j & 7) >> 1) + (j & 1) + 2 * (j >> 3);
        g_wh[co * 144 + (k & ~15) + pos] = __float2half_rn(w[i]);
    }
}

// ---------------- im2col pre-pass: 8 outputs/thread, incremental pointers ----------------
__global__ __launch_bounds__(256) void im2col_kernel(const float* __restrict__ x) {
    int kp = blockIdx.y;       // 0..71
    int slice = blockIdx.z;    // 0..63
    int b = slice >> 3, Dz = slice & 7;
    const float* xp = x + ((size_t)(b * 16) * 8 + Dz) * 9216;
    int k0 = 2 * kp;
    int ci0 = k0 / 9, r0 = k0 - ci0 * 9, kh0 = r0 / 3, kw0 = r0 - kh0 * 3;
    int k1 = k0 + 1;
    int ci1 = k1 / 9, r1 = k1 - ci1 * 9, kh1 = r1 / 3, kw1 = r1 - kh1 * 3;

    int lane = threadIdx.x & 31;
    int warp = threadIdx.x >> 5;
    int p = blockIdx.x * 2048 + warp * 256 + lane;  // lane-consecutive -> coalesced
    int y = p / 94, xx = p - y * 94;
    const float* s0 = xp + (size_t)ci0 * 73728 + (y + kh0) * 96 + xx + kw0;
    const float* s1 = xp + (size_t)ci1 * 73728 + (y + kh1) * 96 + xx + kw1;
    uint32_t* dst = g_im + ((size_t)slice * 72 + kp) * 8836 + p;

    #pragma unroll
    for (int i = 0; i < 8; i++) {
        if (p < HW) dst[0] = packh2(s0[0], s1[0]);
        p += 32; dst += 32;
        xx += 32;
        int step = (xx >= 94) ? 34 : 32;     // +2 row-pad skip on wrap
        xx -= (xx >= 94) ? 94 : 0;
        s0 += step; s1 += step;
    }
}

// ---------------- conv via mma.sync fp16, im2col-fed B, 3-buffer B pipeline ----------------
// A: fp16 [128 m][144 k permuted], cp.async once (region reused as fp16 C stage).
// B: u32 fp16x2 [24 kp][136 n] x 3 chunk buffers, ALL prefetched upfront.
#define KC     48
#define NCHUNK 3
#define BSTR   136
#define NTILE  128
#define ABYTES (128 * 144 * 2)          // 36864
#define BBYTES (24 * BSTR * 4)          // 13056
#define SMEM_TOT (ABYTES + 3 * BBYTES)  // 76032
#define STG_H  136                      // C stage row stride in halves (272 B)

__global__ __launch_bounds__(256, 2) void conv_mma_kernel() {
    extern __shared__ char smc[];
    uint32_t smem_base = smem_u32(smc);

    int tid = threadIdx.x, wid = tid >> 5, lid = tid & 31;
    int gid = lid >> 2, tig = lid & 3;

    int tileBase = blockIdx.x * NTILE;
    int mGroup   = blockIdx.y;           // 0..1
    int bd       = blockIdx.z;           // 0..63 slice
    int b = bd >> 3, Dz = bd & 7;

    const uint32_t* imBase = g_im + (size_t)bd * 72 * 8836 + tileBase;

    // B fill: 24 kp x 32 4-word groups = 768 cpa16, 3/thread
    auto prefetchB = [&](int c) {
        uint32_t bBase = smem_base + ABYTES + (uint32_t)c * BBYTES;
        const uint32_t* src = imBase + (size_t)(c * 24) * 8836;
        #pragma unroll
        for (int i = 0; i < 3; i++) {
            int e = tid + i * 256;          // 0..767
            int kp = e >> 5, t = e & 31;
            cpa16(bBase + (uint32_t)(kp * BSTR + 4 * t) * 4,
                  src + (size_t)kp * 8836 + 4 * t);
        }
        CP_COMMIT();
    };

    // group order: (A + B0), B1, B2  -> wait counts 2, 1, 0 per chunk
    {
        const __half* wsrc = g_wh + (size_t)mGroup * 128 * 144;
        #pragma unroll
        for (int i = 0; i < 9; i++) {
            int e = tid + i * 256;
            int m = e / 18, v = e - m * 18;
            cpa16(smem_base + (uint32_t)(m * 288 + v * 16),
                  wsrc + (size_t)m * 144 + v * 8);
        }
    }
    prefetchB(0);      // commit group 0 (A + B0)
    prefetchB(1);      // group 1
    prefetchB(2);      // group 2

    int m0 = (wid & 1) * 64;
    int n0 = (wid >> 1) * 32;

    float acc[4][4][4];
    #pragma unroll
    for (int i = 0; i < 4; i++)
        #pragma unroll
        for (int j = 0; j < 4; j++)
            #pragma unroll
            for (int q = 0; q < 4; q++) acc[i][j][q] = 0.f;

    const __half* Ah = (const __half*)smc;

    #pragma unroll
    for (int c = 0; c < NCHUNK; c++) {
        if (c == 0)      asm volatile("cp.async.wait_group 2;" ::: "memory");
        else if (c == 1) asm volatile("cp.async.wait_group 1;" ::: "memory");
        else             asm volatile("cp.async.wait_group 0;" ::: "memory");
        __syncthreads();

        const uint32_t* Bcur = (const uint32_t*)(smc + ABYTES + c * BBYTES);

        #pragma unroll
        for (int ks = 0; ks < KC / 16; ks++) {
            int kbA = c * KC + ks * 16;   // A global k base (permuted layout)
            uint32_t a[4][4], bb[4][2];
            #pragma unroll
            for (int mf = 0; mf < 4; mf++) {
                int m = m0 + mf * 16 + gid;
                uint2 v0 = *(const uint2*)(Ah + m * 144 + kbA + 4 * tig);
                uint2 v1 = *(const uint2*)(Ah + (m + 8) * 144 + kbA + 4 * tig);
                a[mf][0] = v0.x;   // A[m][k,k+1]
                a[mf][1] = v1.x;   // A[m+8][k,k+1]
                a[mf][2] = v0.y;   // A[m][k+8,k+9]
                a[mf][3] = v1.y;   // A[m+8][k+8,k+9]
            }
            int kp0 = ks * 8 + tig;
            #pragma unroll
            for (int nf = 0; nf < 4; nf++) {
                int n = n0 + nf * 8 + gid;
                bb[nf][0] = Bcur[kp0 * BSTR + n];            // (k, k+1) fp16x2
                bb[nf][1] = Bcur[(kp0 + 4) * BSTR + n];      // (k+8, k+9)
            }
            #pragma unroll
            for (int mf = 0; mf < 4; mf++)
                #pragma unroll
                for (int nf = 0; nf < 4; nf++)
                    mma16816(acc[mf][nf], a[mf][0], a[mf][1], a[mf][2], a[mf][3],
                             bb[nf][0], bb[nf][1]);
        }
        // no trailing sync: each chunk has its own buffer, nothing is overwritten
    }

    // all warps must finish reading A before it becomes the C stage
    __syncthreads();

    // ---- epilogue: stage C fp16 into dead A region [128 co_loc][STG_H], then coalesced out ----
    __half* stage = (__half*)smc;
    #pragma unroll
    for (int mf = 0; mf < 4; mf++) {
        #pragma unroll
        for (int h2 = 0; h2 < 2; h2++) {
            int col = m0 + mf * 16 + gid + h2 * 8;   // co_local 0..127
            int n = n0 + 2 * tig;
            #pragma unroll
            for (int nf = 0; nf < 4; nf++) {
                *(__half2*)(stage + col * STG_H + n + nf * 8) =
                    __floats2half2_rn(acc[mf][nf][h2 * 2], acc[mf][nf][h2 * 2 + 1]);
            }
        }
    }
    __syncthreads();

    int nvalid = HW - tileBase;
    int segLim = (nvalid >= NTILE) ? 32 : (nvalid >> 2);   // uint2 = 4 halves
    #pragma unroll
    for (int i = 0; i < 16; i++) {
        int e = tid + i * 256;           // 0..4095
        int col = e >> 5, seg = e & 31;
        if (seg < segLim) {
            int co = mGroup * 128 + col;
            int dcap = co & 7, ccap = co >> 3;
            __half* dst = g_u + ((size_t)((b * 8 + dcap) * 8 + Dz) * 32 + ccap) * 8836
                          + tileBase + seg * 4;
            *(uint2*)dst = *(const uint2*)(stage + col * STG_H + seg * 4);
        }
    }
}

// ============================ routing (2 points/thread) ============================
__global__ void init_kernel() {
    int t = threadIdx.x;
    if (t < 64) { g_S1[t] = 0.f; g_S2[t] = 0.f; }
}

__device__ __forceinline__ void blockReduceAtomic(float e[8], int b, float* Sg) {
    __shared__ float red[8][8];
    #pragma unroll
    for (int off = 16; off > 0; off >>= 1)
        #pragma unroll
        for (int d = 0; d < 8; d++) e[d] += __shfl_down_sync(0xffffffffu, e[d], off);
    int lane = threadIdx.x & 31, wp = threadIdx.x >> 5;
    if (lane == 0) {
        #pragma unroll
        for (int d = 0; d < 8; d++) red[wp][d] = e[d];
    }
    __syncthreads();
    if (threadIdx.x < 8) {
        float s = 0.f;
        #pragma unroll
        for (int w_ = 0; w_ < 8; w_++) s += red[w_][threadIdx.x];
        atomicAdd(&Sg[b * 8 + threadIdx.x], s);
    }
}

__global__ __launch_bounds__(256) void gram_iter0_kernel() {
    int b = blockIdx.y;
    int idx = blockIdx.x * 256 + threadIdx.x;
    bool act = idx < HALFB;
    float e[8];
    if (act) {
        int pl = idx * 2;
        int dcap = pl / 8836;
        int hw = pl - dcap * 8836;
        const __half2* up = (const __half2*)(g_u + ((size_t)(b * 8 + dcap) * 256) * 8836 + hw);

        __half2 M2[36];
        #pragma unroll
        for (int i = 0; i < 36; i++) M2[i] = __float2half2_rn(0.f);

        #pragma unroll 4
        for (int c = 0; c < 32; c++) {
            __half2 a2[8];
            #pragma unroll
            for (int d = 0; d < 8; d++) a2[d] = up[(size_t)(d * 32 + c) * 4418];
            int mi = 0;
            #pragma unroll
            for (int d1 = 0; d1 < 8; d1++)
                #pragma unroll
                for (int d2 = d1; d2 < 8; d2++) {
                    M2[mi] = __hfma2(a2[d1], a2[d2], M2[mi]);
                    mi++;
                }
        }

        float rsA[8], rsB[8];
        #pragma unroll
        for (int d = 0; d < 8; d++) { rsA[d] = 0.f; rsB[d] = 0.f; }
        {
            int mi = 0;
            #pragma unroll
            for (int d1 = 0; d1 < 8; d1++)
                #pragma unroll
                for (int d2 = d1; d2 < 8; d2++) {
                    float2 m = __half22float2(M2[mi++]);
                    rsA[d2] += m.x; rsB[d2] += m.y;
                    if (d1 != d2) { rsA[d1] += m.x; rsB[d1] += m.y; }
                }
        }
        float totA = 0.f, totB = 0.f;
        #pragma unroll
        for (int d = 0; d < 8; d++) { totA += rsA[d]; totB += rsB[d]; }
        const float invN = 1.0f / 70688.0f;
        float n2A = totA * invN * invN, n2B = totB * invN * invN;
        float h0A = (n2A / (1.f + n2A)) / sqrtf(n2A + EPSS);
        float h0B = (n2B / (1.f + n2B)) / sqrtf(n2B + EPSS);

        int pg = b * PER_B + pl;
        #pragma unroll
        for (int i = 0; i < 36; i++)
            *(__half2*)(g_M + (size_t)i * NPTS + pg) = M2[i];
        #pragma unroll
        for (int d = 0; d < 8; d++) {
            float bvA = h0A * invN * rsA[d];
            float bvB = h0B * invN * rsB[d];
            *(float2*)(g_bq + (size_t)d * NPTS + pg) = make_float2(bvA, bvB);
            e[d] = expf(bvA) + expf(bvB);
        }
    } else {
        #pragma unroll
        for (int d = 0; d < 8; d++) e[d] = 0.f;
    }
    blockReduceAtomic(e, b, g_S1);
}

__global__ __launch_bounds__(256) void iter1_kernel() {
    int b = blockIdx.y;
    int idx = blockIdx.x * 256 + threadIdx.x;
    bool act = idx < HALFB;
    float e[8];
    if (act) {
        int pg = b * PER_B + idx * 2;
        float2 bl[8];
        float ccA[8], ccB[8];
        #pragma unroll
        for (int d = 0; d < 8; d++) {
            bl[d] = *(const float2*)(g_bq + (size_t)d * NPTS + pg);
            float S = g_S1[b * 8 + d];
            ccA[d] = expf(bl[d].x) / S;
            ccB[d] = expf(bl[d].y) / S;
        }
        float tA[8], tB[8];
        #pragma unroll
        for (int d = 0; d < 8; d++) { tA[d] = 0.f; tB[d] = 0.f; }
        {
            int mi = 0;
            #pragma unroll
            for (int d1 = 0; d1 < 8; d1++)
                #pragma unroll
                for (int d2 = d1; d2 < 8; d2++) {
                    float2 m = __half22float2(*(const __half2*)(g_M + (size_t)mi * NPTS + pg));
                    tA[d2] += m.x * ccA[d1]; tB[d2] += m.y * ccB[d1];
                    if (d1 != d2) { tA[d1] += m.x * ccA[d2]; tB[d1] += m.y * ccB[d2]; }
                    mi++;
                }
        }
        float n2A = 0.f, n2B = 0.f;
        #pragma unroll
        for (int d = 0; d < 8; d++) { n2A += ccA[d] * tA[d]; n2B += ccB[d] * tB[d]; }
        float h1A = (n2A / (1.f + n2A)) / sqrtf(n2A + EPSS);
        float h1B = (n2B / (1.f + n2B)) / sqrtf(n2B + EPSS);
        #pragma unroll
        for (int d = 0; d < 8; d++) {
            float bnA = bl[d].x + h1A * tA[d];
            float bnB = bl[d].y + h1B * tB[d];
            *(float2*)(g_bq + (size_t)d * NPTS + pg) = make_float2(bnA, bnB);
            e[d] = expf(bnA) + expf(bnB);
        }
    } else {
        #pragma unroll
        for (int d = 0; d < 8; d++) e[d] = 0.f;
    }
    blockReduceAtomic(e, b, g_S2);
}

__global__ __launch_bounds__(256) void final_kernel(float* __restrict__ out) {
    int b = blockIdx.y;
    int idx = blockIdx.x * 256 + threadIdx.x;
    if (idx >= HALFB) return;
    int pl = idx * 2;
    int pg = b * PER_B + pl;
    float ccA[8], ccB[8];
    #pragma unroll
    for (int d = 0; d < 8; d++) {
        float2 bv = *(const float2*)(g_bq + (size_t)d * NPTS + pg);
        float S = g_S2[b * 8 + d];
        ccA[d] = expf(bv.x) / S;
        ccB[d] = expf(bv.y) / S;
    }

    int dcap = pl / 8836, hw = pl - dcap * 8836;
    const __half2* up = (const __half2*)(g_u + ((size_t)(b * 8 + dcap) * 256) * 8836 + hw);
    #pragma unroll 4
    for (int c = 0; c < 32; c++) {
        float sA = 0.f, sB = 0.f;
        #pragma unroll
        for (int d = 0; d < 8; d++) {
            float2 uf = __half22float2(up[(size_t)(d * 32 + c) * 4418]);
            sA += ccA[d] * uf.x;
            sB += ccB[d] * uf.y;
        }
        *(float2*)(out + ((size_t)(b * 32 + c) * 8 + dcap) * 8836 + hw) = make_float2(sA, sB);
    }
}

extern "C" void kernel_launch(void* const* d_in, const int* in_sizes, int n_in,
                              void* d_out, int out_size) {
    const float* x = (const float*)d_in[0];
    const float* w = (const float*)d_in[1];
    float* out = (float*)d_out;

    cudaFuncSetAttribute(conv_mma_kernel, cudaFuncAttributeMaxDynamicSharedMemorySize, SMEM_TOT);

    init_kernel<<<1, 64>>>();
    wconv_kernel<<<144, 256>>>(w);

    dim3 igrid(5, 72, 64);   // 2048-p tiles x kp x slices, 8 outputs/thread
    im2col_kernel<<<igrid, 256>>>(x);

    dim3 cgrid(70, 2, 64);   // n-tiles x co-halves x (b,Dz)
    conv_mma_kernel<<<cgrid, 256, SMEM_TOT>>>();

    dim3 rgrid(139, 8);      // ceil(35344/256) x 8 batches, 2 pts/thread
    gram_iter0_kernel<<<rgrid, 256>>>();
    iter1_kernel<<<rgrid, 256>>>();
    final_kernel<<<rgrid, 256>>>(out);
}